// round 3
// baseline (speedup 1.0000x reference)
#include <cuda_runtime.h>

#define E_EDGES 1000000
#define N_NODES 50000
#define DIM     64
#define MSG     256

// ---------------- scratch (static device globals: no allocations) ----------
__device__ __align__(16) float g_Ps[N_NODES * MSG];   // x_s @ W1[0:64]
__device__ __align__(16) float g_Pt[N_NODES * MSG];   // x_t @ W1[64:128]
__device__ __align__(16) float g_c[MSG];              // x_u @ W1[192:256] + b1
__device__ int   g_idx64;                             // edge_index dtype flag

// packed fp32x2 FMA (sm_103a): 2x FFMA throughput vs 3-reg FFMA
__device__ __forceinline__ float2 ffma2(float2 a, float2 b, float2 c) {
    float2 d;
    asm("fma.rn.f32x2 %0, %1, %2, %3;"
        : "=l"(reinterpret_cast<unsigned long long &>(d))
        : "l"(reinterpret_cast<unsigned long long &>(a)),
          "l"(reinterpret_cast<unsigned long long &>(b)),
          "l"(reinterpret_cast<unsigned long long &>(c)));
    return d;
}

__device__ __forceinline__ float lrelu(float v) {
    return v >= 0.0f ? v : 0.01f * v;
}

// ---------------- dtype detector: int64 edge_index has zero high words -----
__global__ void detect_idx_kernel(const unsigned int* __restrict__ idx) {
    if (threadIdx.x == 0) {
        int is64 = 1;
        for (int i = 0; i < 64; i++)
            if (idx[2 * i + 1] != 0u) { is64 = 0; break; }
        g_idx64 = is64;
    }
}

// ---------------- c = b1 + x_u @ W1[192:256] -------------------------------
__global__ void cvec_kernel(const float* __restrict__ W1,
                            const float* __restrict__ b1,
                            const float* __restrict__ xu) {
    int j = threadIdx.x;
    float acc = b1[j];
#pragma unroll 8
    for (int k = 0; k < DIM; k++)
        acc = fmaf(xu[k], W1[(192 + k) * MSG + j], acc);
    g_c[j] = acc;
}

// ---------------- P = X[N,64] @ Wsub[64,256] -------------------------------
// block: 64 rows x 256 outputs, 256 threads, thread = 8 rows x 8 cols
__global__ __launch_bounds__(256, 1)
void node_pre_kernel(const float* __restrict__ X, const float* __restrict__ Wsub,
                     int which, int N) {
    extern __shared__ float sm[];
    float* sW = sm;              // 64*256 = 16384 floats
    float* sA = sm + 16384;      // 64*68  = 4352 floats (padded rows)
    float* P  = which ? g_Pt : g_Ps;

    int t = threadIdx.x;
    int row0 = blockIdx.x * 64;

    // weight tile: 4096 float4 = 16 iterations
#pragma unroll
    for (int i = 0; i < 16; i++) {
        int idx = t + i * 256;
        reinterpret_cast<float4*>(sW)[idx] = reinterpret_cast<const float4*>(Wsub)[idx];
    }
    // A tile: 64 rows x 16 float4 = 1024 float4 = 4 iterations
#pragma unroll
    for (int i = 0; i < 4; i++) {
        int f = t + i * 256;           // float4 id 0..1023
        int r = f >> 4, q = f & 15;
        float4 v = make_float4(0.f, 0.f, 0.f, 0.f);
        if (row0 + r < N)
            v = reinterpret_cast<const float4*>(X)[(row0 + r) * 16 + q];
        *reinterpret_cast<float4*>(&sA[r * 68 + q * 4]) = v;
    }
    __syncthreads();

    int tx = t & 31, ty = t >> 5;
    float2 acc[8][4];
#pragma unroll
    for (int e = 0; e < 8; e++)
#pragma unroll
        for (int j = 0; j < 4; j++) acc[e][j] = make_float2(0.f, 0.f);

    for (int k4 = 0; k4 < 64; k4 += 4) {
        float4 a[8];
#pragma unroll
        for (int e = 0; e < 8; e++)
            a[e] = *reinterpret_cast<const float4*>(&sA[(ty * 8 + e) * 68 + k4]);
#pragma unroll
        for (int kk = 0; kk < 4; kk++) {
            float4 b0 = *reinterpret_cast<const float4*>(&sW[(k4 + kk) * 256 + tx * 4]);
            float4 b1 = *reinterpret_cast<const float4*>(&sW[(k4 + kk) * 256 + 128 + tx * 4]);
#pragma unroll
            for (int e = 0; e < 8; e++) {
                float av = (kk == 0) ? a[e].x : (kk == 1) ? a[e].y : (kk == 2) ? a[e].z : a[e].w;
                float2 ad = make_float2(av, av);
                acc[e][0] = ffma2(ad, make_float2(b0.x, b0.y), acc[e][0]);
                acc[e][1] = ffma2(ad, make_float2(b0.z, b0.w), acc[e][1]);
                acc[e][2] = ffma2(ad, make_float2(b1.x, b1.y), acc[e][2]);
                acc[e][3] = ffma2(ad, make_float2(b1.z, b1.w), acc[e][3]);
            }
        }
    }

#pragma unroll
    for (int e = 0; e < 8; e++) {
        int r = row0 + ty * 8 + e;
        if (r < N) {
            float4 o0 = make_float4(acc[e][0].x, acc[e][0].y, acc[e][1].x, acc[e][1].y);
            float4 o1 = make_float4(acc[e][2].x, acc[e][2].y, acc[e][3].x, acc[e][3].y);
            *reinterpret_cast<float4*>(&P[r * 256 + tx * 4])       = o0;
            *reinterpret_cast<float4*>(&P[r * 256 + 128 + tx * 4]) = o1;
        }
    }
}

// ---------------- fused per-edge kernel ------------------------------------
// block = 64 edges, 256 threads
// GEMM1: [64,64]@[64,256] (ea @ W1c), + gathered P_s/P_t + c, LeakyReLU -> smem
// GEMM2: [64,256]@[256,64] (+b2), RMSNorm, *gamma -> out
__global__ __launch_bounds__(256, 1)
void edge_kernel(const float* __restrict__ ea, const void* __restrict__ eidx,
                 const float* __restrict__ W1, const float* __restrict__ W2,
                 const float* __restrict__ b2, const float* __restrict__ gamma,
                 float* __restrict__ out) {
    extern __shared__ float sm[];
    float* sW1c = sm;                                   // 16384 floats
    float* sW2  = sm + 16384;                           // 16384 floats
    float* sH1  = sm + 32768;                           // 64*260 = 16640 floats
    float* sA   = sm + 49408;                           // 64*68  = 4352 floats
    int*   sIdx = reinterpret_cast<int*>(sm + 53760);   // 128 ints = 128 floats

    int t  = threadIdx.x;
    int e0 = blockIdx.x * 64;

    const float* W1c = W1 + 128 * 256;
    // weight tiles: 4096 float4 each
#pragma unroll
    for (int i = 0; i < 16; i++) {
        int idx = t + i * 256;
        reinterpret_cast<float4*>(sW1c)[idx] = reinterpret_cast<const float4*>(W1c)[idx];
        reinterpret_cast<float4*>(sW2)[idx]  = reinterpret_cast<const float4*>(W2)[idx];
    }
    // edge_attr tile: 64 rows x 16 float4 = 1024 float4
#pragma unroll
    for (int i = 0; i < 4; i++) {
        int f = t + i * 256;
        int r = f >> 4, q = f & 15;
        *reinterpret_cast<float4*>(&sA[r * 68 + q * 4]) =
            reinterpret_cast<const float4*>(ea)[(e0 + r) * 16 + q];
    }
    if (t < 128) {
        int e = t & 63;
        long long pos = (long long)((t < 64) ? 0 : E_EDGES) + e0 + e;
        int v;
        if (g_idx64) v = (int)reinterpret_cast<const long long*>(eidx)[pos];
        else         v = reinterpret_cast<const int*>(eidx)[pos];
        sIdx[t] = v;
    }
    __syncthreads();

    // ---------- GEMM1: thread = 8 edges x 8 cols {tx*4+j, 128+tx*4+j} ----
    int tx = t & 31, ty = t >> 5;
    float2 acc[8][4];
#pragma unroll
    for (int e = 0; e < 8; e++)
#pragma unroll
        for (int j = 0; j < 4; j++) acc[e][j] = make_float2(0.f, 0.f);

    for (int k4 = 0; k4 < 64; k4 += 4) {
        float4 a[8];
#pragma unroll
        for (int e = 0; e < 8; e++)
            a[e] = *reinterpret_cast<const float4*>(&sA[(ty * 8 + e) * 68 + k4]);
#pragma unroll
        for (int kk = 0; kk < 4; kk++) {
            float4 b0 = *reinterpret_cast<const float4*>(&sW1c[(k4 + kk) * 256 + tx * 4]);
            float4 b1 = *reinterpret_cast<const float4*>(&sW1c[(k4 + kk) * 256 + 128 + tx * 4]);
#pragma unroll
            for (int e = 0; e < 8; e++) {
                float av = (kk == 0) ? a[e].x : (kk == 1) ? a[e].y : (kk == 2) ? a[e].z : a[e].w;
                float2 ad = make_float2(av, av);
                acc[e][0] = ffma2(ad, make_float2(b0.x, b0.y), acc[e][0]);
                acc[e][1] = ffma2(ad, make_float2(b0.z, b0.w), acc[e][1]);
                acc[e][2] = ffma2(ad, make_float2(b1.x, b1.y), acc[e][2]);
                acc[e][3] = ffma2(ad, make_float2(b1.z, b1.w), acc[e][3]);
            }
        }
    }

    // ---------- epilogue1: + P_s[src] + P_t[tgt] + c, LeakyReLU -> sH1 ----
    float4 c0 = *reinterpret_cast<const float4*>(&g_c[tx * 4]);
    float4 c1 = *reinterpret_cast<const float4*>(&g_c[128 + tx * 4]);
#pragma unroll
    for (int e = 0; e < 8; e++) {
        int eg = ty * 8 + e;
        int s  = sIdx[eg];
        int tg = sIdx[64 + eg];
        float4 ps0 = *reinterpret_cast<const float4*>(&g_Ps[s * 256 + tx * 4]);
        float4 ps1 = *reinterpret_cast<const float4*>(&g_Ps[s * 256 + 128 + tx * 4]);
        float4 pt0 = *reinterpret_cast<const float4*>(&g_Pt[tg * 256 + tx * 4]);
        float4 pt1 = *reinterpret_cast<const float4*>(&g_Pt[tg * 256 + 128 + tx * 4]);
        float4 o0, o1;
        o0.x = lrelu(acc[e][0].x + ps0.x + pt0.x + c0.x);
        o0.y = lrelu(acc[e][0].y + ps0.y + pt0.y + c0.y);
        o0.z = lrelu(acc[e][1].x + ps0.z + pt0.z + c0.z);
        o0.w = lrelu(acc[e][1].y + ps0.w + pt0.w + c0.w);
        o1.x = lrelu(acc[e][2].x + ps1.x + pt1.x + c1.x);
        o1.y = lrelu(acc[e][2].y + ps1.y + pt1.y + c1.y);
        o1.z = lrelu(acc[e][3].x + ps1.z + pt1.z + c1.z);
        o1.w = lrelu(acc[e][3].y + ps1.w + pt1.w + c1.w);
        *reinterpret_cast<float4*>(&sH1[eg * 260 + tx * 4])       = o0;
        *reinterpret_cast<float4*>(&sH1[eg * 260 + 128 + tx * 4]) = o1;
    }
    __syncthreads();

    // ---------- GEMM2: thread = 2 edges x 8 cols {tx2*4+j, 32+tx2*4+j} ---
    int tx2 = t & 7, ty2 = t >> 3;
    float2 a2[2][4];
#pragma unroll
    for (int i = 0; i < 2; i++)
#pragma unroll
        for (int j = 0; j < 4; j++) a2[i][j] = make_float2(0.f, 0.f);

    for (int k4 = 0; k4 < 256; k4 += 4) {
        float4 ha[2];
#pragma unroll
        for (int i = 0; i < 2; i++)
            ha[i] = *reinterpret_cast<const float4*>(&sH1[(ty2 * 2 + i) * 260 + k4]);
#pragma unroll
        for (int kk = 0; kk < 4; kk++) {
            float4 b0 = *reinterpret_cast<const float4*>(&sW2[(k4 + kk) * 64 + tx2 * 4]);
            float4 b1 = *reinterpret_cast<const float4*>(&sW2[(k4 + kk) * 64 + 32 + tx2 * 4]);
#pragma unroll
            for (int i = 0; i < 2; i++) {
                float av = (kk == 0) ? ha[i].x : (kk == 1) ? ha[i].y : (kk == 2) ? ha[i].z : ha[i].w;
                float2 ad = make_float2(av, av);
                a2[i][0] = ffma2(ad, make_float2(b0.x, b0.y), a2[i][0]);
                a2[i][1] = ffma2(ad, make_float2(b0.z, b0.w), a2[i][1]);
                a2[i][2] = ffma2(ad, make_float2(b1.x, b1.y), a2[i][2]);
                a2[i][3] = ffma2(ad, make_float2(b1.z, b1.w), a2[i][3]);
            }
        }
    }

    // ---------- epilogue2: + b2, RMSNorm, * gamma, store ------------------
    float4 bb0 = *reinterpret_cast<const float4*>(&b2[tx2 * 4]);
    float4 bb1 = *reinterpret_cast<const float4*>(&b2[32 + tx2 * 4]);
    float4 gg0 = *reinterpret_cast<const float4*>(&gamma[tx2 * 4]);
    float4 gg1 = *reinterpret_cast<const float4*>(&gamma[32 + tx2 * 4]);
#pragma unroll
    for (int i = 0; i < 2; i++) {
        float h0 = a2[i][0].x + bb0.x;
        float h1 = a2[i][0].y + bb0.y;
        float h2 = a2[i][1].x + bb0.z;
        float h3 = a2[i][1].y + bb0.w;
        float h4 = a2[i][2].x + bb1.x;
        float h5 = a2[i][2].y + bb1.y;
        float h6 = a2[i][3].x + bb1.z;
        float h7 = a2[i][3].y + bb1.w;
        float ssq = h0 * h0 + h1 * h1 + h2 * h2 + h3 * h3
                  + h4 * h4 + h5 * h5 + h6 * h6 + h7 * h7;
        // reduce across the 8 lanes (tx2) sharing these edges
        ssq += __shfl_xor_sync(0xffffffffu, ssq, 1);
        ssq += __shfl_xor_sync(0xffffffffu, ssq, 2);
        ssq += __shfl_xor_sync(0xffffffffu, ssq, 4);
        float scale = rsqrtf(ssq * (1.0f / 64.0f) + 1.1920929e-07f);
        int eg = e0 + ty2 * 2 + i;
        float4 o0 = make_float4(h0 * scale * gg0.x, h1 * scale * gg0.y,
                                h2 * scale * gg0.z, h3 * scale * gg0.w);
        float4 o1 = make_float4(h4 * scale * gg1.x, h5 * scale * gg1.y,
                                h6 * scale * gg1.z, h7 * scale * gg1.w);
        *reinterpret_cast<float4*>(&out[eg * 64 + tx2 * 4])      = o0;
        *reinterpret_cast<float4*>(&out[eg * 64 + 32 + tx2 * 4]) = o1;
    }
}

// ---------------- launch ----------------------------------------------------
extern "C" void kernel_launch(void* const* d_in, const int* in_sizes, int n_in,
                              void* d_out, int out_size) {
    (void)in_sizes; (void)n_in; (void)out_size;
    const float* x_s   = (const float*)d_in[0];
    const float* x_t   = (const float*)d_in[1];
    const void*  eidx  = d_in[2];
    const float* ea    = (const float*)d_in[3];
    const float* xu    = (const float*)d_in[4];
    const float* W1    = (const float*)d_in[5];
    const float* b1    = (const float*)d_in[6];
    const float* W2    = (const float*)d_in[7];
    const float* b2    = (const float*)d_in[8];
    const float* gamma = (const float*)d_in[9];
    float* out = (float*)d_out;

    const int SMEM_PRE  = (16384 + 64 * 68) * 4;                           // 82944 B
    const int SMEM_MAIN = (16384 + 16384 + 64 * 260 + 64 * 68 + 128) * 4;  // 215552 B

    cudaFuncSetAttribute(node_pre_kernel,
                         cudaFuncAttributeMaxDynamicSharedMemorySize, SMEM_PRE);
    cudaFuncSetAttribute(edge_kernel,
                         cudaFuncAttributeMaxDynamicSharedMemorySize, SMEM_MAIN);

    detect_idx_kernel<<<1, 32>>>((const unsigned int*)eidx);
    cvec_kernel<<<1, MSG>>>(W1, b1, xu);

    int pgrid = (N_NODES + 63) / 64;
    node_pre_kernel<<<pgrid, 256, SMEM_PRE>>>(x_s, W1,            0, N_NODES);
    node_pre_kernel<<<pgrid, 256, SMEM_PRE>>>(x_t, W1 + 64 * 256, 1, N_NODES);

    edge_kernel<<<E_EDGES / 64, 256, SMEM_MAIN>>>(ea, eidx, W1, W2, b2, gamma, out);
}

// round 4
// speedup vs baseline: 1.0718x; 1.0718x over previous
#include <cuda_runtime.h>

#define E_EDGES 1000000
#define N_NODES 50000
#define DIM     64
#define MSG     256
#define NTILES  (E_EDGES / 64)

// ---------------- scratch (static device globals: no allocations) ----------
__device__ __align__(16) float g_Ps[N_NODES * MSG];   // x_s @ W1[0:64]
__device__ __align__(16) float g_Pt[N_NODES * MSG];   // x_t @ W1[64:128]
__device__ __align__(16) float g_c[MSG];              // x_u @ W1[192:256] + b1
__device__ int   g_idx64;                             // edge_index dtype flag

// packed fp32x2 FMA (sm_103a): 2x FFMA throughput vs 3-reg FFMA
__device__ __forceinline__ float2 ffma2(float2 a, float2 b, float2 c) {
    float2 d;
    asm("fma.rn.f32x2 %0, %1, %2, %3;"
        : "=l"(reinterpret_cast<unsigned long long &>(d))
        : "l"(reinterpret_cast<unsigned long long &>(a)),
          "l"(reinterpret_cast<unsigned long long &>(b)),
          "l"(reinterpret_cast<unsigned long long &>(c)));
    return d;
}

__device__ __forceinline__ float lrelu(float v) {
    return v >= 0.0f ? v : 0.01f * v;
}

__device__ __forceinline__ void cp16(float* s, const float4* g) {
    unsigned int sa = (unsigned int)__cvta_generic_to_shared(s);
    asm volatile("cp.async.ca.shared.global [%0], [%1], 16;" :: "r"(sa), "l"(g));
}
__device__ __forceinline__ void cp_commit() {
    asm volatile("cp.async.commit_group;");
}
__device__ __forceinline__ void cp_wait_all() {
    asm volatile("cp.async.wait_group 0;");
}

// ---------------- dtype detector: int64 edge_index has zero high words -----
__global__ void detect_idx_kernel(const unsigned int* __restrict__ idx) {
    if (threadIdx.x == 0) {
        int is64 = 1;
        for (int i = 0; i < 64; i++)
            if (idx[2 * i + 1] != 0u) { is64 = 0; break; }
        g_idx64 = is64;
    }
}

// ---------------- c = b1 + x_u @ W1[192:256] -------------------------------
__global__ void cvec_kernel(const float* __restrict__ W1,
                            const float* __restrict__ b1,
                            const float* __restrict__ xu) {
    int j = threadIdx.x;
    float acc = b1[j];
#pragma unroll 8
    for (int k = 0; k < DIM; k++)
        acc = fmaf(xu[k], W1[(192 + k) * MSG + j], acc);
    g_c[j] = acc;
}

// ---------------- P = X[N,64] @ Wsub[64,256] -------------------------------
__global__ __launch_bounds__(256, 1)
void node_pre_kernel(const float* __restrict__ X, const float* __restrict__ Wsub,
                     int which, int N) {
    extern __shared__ float sm[];
    float* sW = sm;              // 16384
    float* sA = sm + 16384;      // 64*68
    float* P  = which ? g_Pt : g_Ps;

    int t = threadIdx.x;
    int row0 = blockIdx.x * 64;

#pragma unroll
    for (int i = 0; i < 16; i++) {
        int idx = t + i * 256;
        reinterpret_cast<float4*>(sW)[idx] = reinterpret_cast<const float4*>(Wsub)[idx];
    }
#pragma unroll
    for (int i = 0; i < 4; i++) {
        int f = t + i * 256;
        int r = f >> 4, q = f & 15;
        float4 v = make_float4(0.f, 0.f, 0.f, 0.f);
        if (row0 + r < N)
            v = reinterpret_cast<const float4*>(X)[(row0 + r) * 16 + q];
        *reinterpret_cast<float4*>(&sA[r * 68 + q * 4]) = v;
    }
    __syncthreads();

    int tx = t & 31, ty = t >> 5;
    float2 acc[8][4];
#pragma unroll
    for (int e = 0; e < 8; e++)
#pragma unroll
        for (int j = 0; j < 4; j++) acc[e][j] = make_float2(0.f, 0.f);

    for (int k4 = 0; k4 < 64; k4 += 4) {
        float4 a[8];
#pragma unroll
        for (int e = 0; e < 8; e++)
            a[e] = *reinterpret_cast<const float4*>(&sA[(ty * 8 + e) * 68 + k4]);
#pragma unroll
        for (int kk = 0; kk < 4; kk++) {
            float4 b0 = *reinterpret_cast<const float4*>(&sW[(k4 + kk) * 256 + tx * 4]);
            float4 b1 = *reinterpret_cast<const float4*>(&sW[(k4 + kk) * 256 + 128 + tx * 4]);
#pragma unroll
            for (int e = 0; e < 8; e++) {
                float av = (kk == 0) ? a[e].x : (kk == 1) ? a[e].y : (kk == 2) ? a[e].z : a[e].w;
                float2 ad = make_float2(av, av);
                acc[e][0] = ffma2(ad, make_float2(b0.x, b0.y), acc[e][0]);
                acc[e][1] = ffma2(ad, make_float2(b0.z, b0.w), acc[e][1]);
                acc[e][2] = ffma2(ad, make_float2(b1.x, b1.y), acc[e][2]);
                acc[e][3] = ffma2(ad, make_float2(b1.z, b1.w), acc[e][3]);
            }
        }
    }

#pragma unroll
    for (int e = 0; e < 8; e++) {
        int r = row0 + ty * 8 + e;
        if (r < N) {
            float4 o0 = make_float4(acc[e][0].x, acc[e][0].y, acc[e][1].x, acc[e][1].y);
            float4 o1 = make_float4(acc[e][2].x, acc[e][2].y, acc[e][3].x, acc[e][3].y);
            *reinterpret_cast<float4*>(&P[r * 256 + tx * 4])       = o0;
            *reinterpret_cast<float4*>(&P[r * 256 + 128 + tx * 4]) = o1;
        }
    }
}

// ---------------- persistent fused per-edge kernel -------------------------
// Weights resident in smem for the whole kernel; tiles of 64 edges streamed
// through a cp.async double buffer (ea + idx), with LDG-early/STS-late idx.
__global__ __launch_bounds__(256, 1)
void edge_kernel(const float* __restrict__ ea, const void* __restrict__ eidx,
                 const float* __restrict__ W1, const float* __restrict__ W2,
                 const float* __restrict__ b2, const float* __restrict__ gamma,
                 float* __restrict__ out) {
    extern __shared__ float sm[];
    float* sW1c  = sm;                                    // 16384 floats
    float* sW2   = sm + 16384;                            // 16384 floats
    float* sH1   = sm + 32768;                            // 64*260 = 16640
    float* sAbuf = sm + 49408;                            // 2 * 64*64 = 8192
    int*   sIbuf = reinterpret_cast<int*>(sm + 57600);    // 2 * 128 ints

    int t  = threadIdx.x;
    int tx = t & 31, ty = t >> 5;
    int tx2 = t & 7, ty2 = t >> 3;

    // ---- one-time: weights into smem ----
    const float* W1c = W1 + 128 * 256;
#pragma unroll
    for (int i = 0; i < 16; i++) {
        int idx = t + i * 256;
        reinterpret_cast<float4*>(sW1c)[idx] = reinterpret_cast<const float4*>(W1c)[idx];
        reinterpret_cast<float4*>(sW2)[idx]  = reinterpret_cast<const float4*>(W2)[idx];
    }
    int idx64 = g_idx64;
    float4 c0 = *reinterpret_cast<const float4*>(&g_c[tx * 4]);
    float4 c1 = *reinterpret_cast<const float4*>(&g_c[128 + tx * 4]);

    // ---- prologue: prefetch first tile ----
    int tile = blockIdx.x;
    const float4* ea4 = reinterpret_cast<const float4*>(ea);
    if (tile < NTILES) {
#pragma unroll
        for (int i = 0; i < 4; i++) {
            int f = t + i * 256;
            cp16(&sAbuf[f * 4], ea4 + (long long)tile * 1024 + f);
        }
        if (t < 128) {
            int e = t & 63;
            long long pos = (long long)((t < 64) ? 0 : E_EDGES) + (long long)tile * 64 + e;
            int v;
            if (idx64) v = (int)reinterpret_cast<const long long*>(eidx)[pos];
            else       v = reinterpret_cast<const int*>(eidx)[pos];
            sIbuf[t] = v;
        }
    }
    cp_commit();

    int buf = 0;
    for (; tile < NTILES; tile += gridDim.x) {
        float* sA   = sAbuf + buf * 4096;
        int*   sIdx = sIbuf + buf * 128;
        float* sAn  = sAbuf + (buf ^ 1) * 4096;
        int*   sIdxn = sIbuf + (buf ^ 1) * 128;
        int ntile = tile + gridDim.x;

        cp_wait_all();
        __syncthreads();   // sA/sIdx ready; sH1 free (prev GEMM2 done)

        // kick off next tile's ea stream + idx loads (STS deferred to end)
        int nidxv = 0;
        if (ntile < NTILES) {
#pragma unroll
            for (int i = 0; i < 4; i++) {
                int f = t + i * 256;
                cp16(&sAn[f * 4], ea4 + (long long)ntile * 1024 + f);
            }
            if (t < 128) {
                int e = t & 63;
                long long pos = (long long)((t < 64) ? 0 : E_EDGES) + (long long)ntile * 64 + e;
                if (idx64) nidxv = (int)reinterpret_cast<const long long*>(eidx)[pos];
                else       nidxv = reinterpret_cast<const int*>(eidx)[pos];
            }
        }
        cp_commit();

        // ---------- GEMM1: thread = 8 edges x 8 cols ----------
        float2 acc[8][4];
#pragma unroll
        for (int e = 0; e < 8; e++)
#pragma unroll
            for (int j = 0; j < 4; j++) acc[e][j] = make_float2(0.f, 0.f);

        for (int k4 = 0; k4 < 64; k4 += 4) {
            float4 a[8];
#pragma unroll
            for (int e = 0; e < 8; e++)
                a[e] = *reinterpret_cast<const float4*>(&sA[(ty * 8 + e) * 64 + k4]);
#pragma unroll
            for (int kk = 0; kk < 4; kk++) {
                float4 b0 = *reinterpret_cast<const float4*>(&sW1c[(k4 + kk) * 256 + tx * 4]);
                float4 b1 = *reinterpret_cast<const float4*>(&sW1c[(k4 + kk) * 256 + 128 + tx * 4]);
#pragma unroll
                for (int e = 0; e < 8; e++) {
                    float av = (kk == 0) ? a[e].x : (kk == 1) ? a[e].y : (kk == 2) ? a[e].z : a[e].w;
                    float2 ad = make_float2(av, av);
                    acc[e][0] = ffma2(ad, make_float2(b0.x, b0.y), acc[e][0]);
                    acc[e][1] = ffma2(ad, make_float2(b0.z, b0.w), acc[e][1]);
                    acc[e][2] = ffma2(ad, make_float2(b1.x, b1.y), acc[e][2]);
                    acc[e][3] = ffma2(ad, make_float2(b1.z, b1.w), acc[e][3]);
                }
            }
        }

        // ---------- epilogue1: + P_s[src] + P_t[tgt] + c, LeakyReLU -> sH1 -
#pragma unroll
        for (int e = 0; e < 8; e++) {
            int eg = ty * 8 + e;
            int s  = sIdx[eg];
            int tg = sIdx[64 + eg];
            float4 ps0 = *reinterpret_cast<const float4*>(&g_Ps[s * 256 + tx * 4]);
            float4 ps1 = *reinterpret_cast<const float4*>(&g_Ps[s * 256 + 128 + tx * 4]);
            float4 pt0 = *reinterpret_cast<const float4*>(&g_Pt[tg * 256 + tx * 4]);
            float4 pt1 = *reinterpret_cast<const float4*>(&g_Pt[tg * 256 + 128 + tx * 4]);
            float4 o0, o1;
            o0.x = lrelu(acc[e][0].x + ps0.x + pt0.x + c0.x);
            o0.y = lrelu(acc[e][0].y + ps0.y + pt0.y + c0.y);
            o0.z = lrelu(acc[e][1].x + ps0.z + pt0.z + c0.z);
            o0.w = lrelu(acc[e][1].y + ps0.w + pt0.w + c0.w);
            o1.x = lrelu(acc[e][2].x + ps1.x + pt1.x + c1.x);
            o1.y = lrelu(acc[e][2].y + ps1.y + pt1.y + c1.y);
            o1.z = lrelu(acc[e][3].x + ps1.z + pt1.z + c1.z);
            o1.w = lrelu(acc[e][3].y + ps1.w + pt1.w + c1.w);
            *reinterpret_cast<float4*>(&sH1[eg * 260 + tx * 4])       = o0;
            *reinterpret_cast<float4*>(&sH1[eg * 260 + 128 + tx * 4]) = o1;
        }
        __syncthreads();

        // ---------- GEMM2: thread = 2 edges x 8 cols ----------
        float2 a2[2][4];
#pragma unroll
        for (int i = 0; i < 2; i++)
#pragma unroll
            for (int j = 0; j < 4; j++) a2[i][j] = make_float2(0.f, 0.f);

        for (int k4 = 0; k4 < 256; k4 += 4) {
            float4 ha[2];
#pragma unroll
            for (int i = 0; i < 2; i++)
                ha[i] = *reinterpret_cast<const float4*>(&sH1[(ty2 * 2 + i) * 260 + k4]);
#pragma unroll
            for (int kk = 0; kk < 4; kk++) {
                float4 b0 = *reinterpret_cast<const float4*>(&sW2[(k4 + kk) * 64 + tx2 * 4]);
                float4 b1 = *reinterpret_cast<const float4*>(&sW2[(k4 + kk) * 64 + 32 + tx2 * 4]);
#pragma unroll
                for (int i = 0; i < 2; i++) {
                    float av = (kk == 0) ? ha[i].x : (kk == 1) ? ha[i].y : (kk == 2) ? ha[i].z : ha[i].w;
                    float2 ad = make_float2(av, av);
                    a2[i][0] = ffma2(ad, make_float2(b0.x, b0.y), a2[i][0]);
                    a2[i][1] = ffma2(ad, make_float2(b0.z, b0.w), a2[i][1]);
                    a2[i][2] = ffma2(ad, make_float2(b1.x, b1.y), a2[i][2]);
                    a2[i][3] = ffma2(ad, make_float2(b1.z, b1.w), a2[i][3]);
                }
            }
        }

        // ---------- epilogue2: + b2, RMSNorm, * gamma, store --------------
        float4 bb0 = *reinterpret_cast<const float4*>(&b2[tx2 * 4]);
        float4 bb1 = *reinterpret_cast<const float4*>(&b2[32 + tx2 * 4]);
        float4 gg0 = *reinterpret_cast<const float4*>(&gamma[tx2 * 4]);
        float4 gg1 = *reinterpret_cast<const float4*>(&gamma[32 + tx2 * 4]);
#pragma unroll
        for (int i = 0; i < 2; i++) {
            float h0 = a2[i][0].x + bb0.x;
            float h1 = a2[i][0].y + bb0.y;
            float h2 = a2[i][1].x + bb0.z;
            float h3 = a2[i][1].y + bb0.w;
            float h4 = a2[i][2].x + bb1.x;
            float h5 = a2[i][2].y + bb1.y;
            float h6 = a2[i][3].x + bb1.z;
            float h7 = a2[i][3].y + bb1.w;
            float ssq = h0 * h0 + h1 * h1 + h2 * h2 + h3 * h3
                      + h4 * h4 + h5 * h5 + h6 * h6 + h7 * h7;
            ssq += __shfl_xor_sync(0xffffffffu, ssq, 1);
            ssq += __shfl_xor_sync(0xffffffffu, ssq, 2);
            ssq += __shfl_xor_sync(0xffffffffu, ssq, 4);
            float scale = rsqrtf(ssq * (1.0f / 64.0f) + 1.1920929e-07f);
            int eg = tile * 64 + ty2 * 2 + i;
            float4 o0 = make_float4(h0 * scale * gg0.x, h1 * scale * gg0.y,
                                    h2 * scale * gg0.z, h3 * scale * gg0.w);
            float4 o1 = make_float4(h4 * scale * gg1.x, h5 * scale * gg1.y,
                                    h6 * scale * gg1.z, h7 * scale * gg1.w);
            *reinterpret_cast<float4*>(&out[eg * 64 + tx2 * 4])      = o0;
            *reinterpret_cast<float4*>(&out[eg * 64 + 32 + tx2 * 4]) = o1;
        }

        // deferred idx STS for next tile (visible after next top-of-loop sync)
        if (ntile < NTILES && t < 128) sIdxn[t] = nidxv;
        buf ^= 1;
    }
}

// ---------------- launch ----------------------------------------------------
extern "C" void kernel_launch(void* const* d_in, const int* in_sizes, int n_in,
                              void* d_out, int out_size) {
    (void)in_sizes; (void)n_in; (void)out_size;
    const float* x_s   = (const float*)d_in[0];
    const float* x_t   = (const float*)d_in[1];
    const void*  eidx  = d_in[2];
    const float* ea    = (const float*)d_in[3];
    const float* xu    = (const float*)d_in[4];
    const float* W1    = (const float*)d_in[5];
    const float* b1    = (const float*)d_in[6];
    const float* W2    = (const float*)d_in[7];
    const float* b2    = (const float*)d_in[8];
    const float* gamma = (const float*)d_in[9];
    float* out = (float*)d_out;

    const int SMEM_PRE  = (16384 + 64 * 68) * 4;                    // 82944 B
    const int SMEM_MAIN = (16384 + 16384 + 16640 + 8192 + 256) * 4; // 231424 B

    cudaFuncSetAttribute(node_pre_kernel,
                         cudaFuncAttributeMaxDynamicSharedMemorySize, SMEM_PRE);
    cudaFuncSetAttribute(edge_kernel,
                         cudaFuncAttributeMaxDynamicSharedMemorySize, SMEM_MAIN);

    int nsm = 148;
    cudaDeviceGetAttribute(&nsm, cudaDevAttrMultiProcessorCount, 0);

    detect_idx_kernel<<<1, 32>>>((const unsigned int*)eidx);
    cvec_kernel<<<1, MSG>>>(W1, b1, xu);

    int pgrid = (N_NODES + 63) / 64;
    node_pre_kernel<<<pgrid, 256, SMEM_PRE>>>(x_s, W1,            0, N_NODES);
    node_pre_kernel<<<pgrid, 256, SMEM_PRE>>>(x_t, W1 + 64 * 256, 1, N_NODES);

    edge_kernel<<<nsm, 256, SMEM_MAIN>>>(ea, eidx, W1, W2, b2, gamma, out);
}